// round 11
// baseline (speedup 1.0000x reference)
#include <cuda_runtime.h>
#include <cuda_bf16.h>
#include <math.h>

#define NN 100000
#define EE 1600000
#define D  128
#define BN_EPS 1e-5f

// ---------------- scratch (device globals; allocation-free kernel_launch) ----
__device__ float g_h [NN * D];
__device__ float g_y [NN * D];
__device__ float g_xa[NN * D];
__device__ float g_xb[NN * D];

__device__ int   g_deg[NN];
__device__ float g_dinv[NN];
__device__ int   g_incl[NN];
__device__ int   g_start[NN];
__device__ int   g_cursor[NN];
__device__ int   g_bsum[256];
__device__ int   g_boff[256];

__device__ int   g_csr_src[EE];
__device__ float g_csr_w [EE];

__device__ float g_sum[D], g_sq[D], g_scale[D], g_shift[D];

__device__ int   g_is64;

// W splits, 6 layers, tile-blocked layout (32768 B per layer per buffer)
__device__ unsigned short g_wh[6 * D * D];
__device__ unsigned short g_wl[6 * D * D];

// ---------------- edge-index dtype detection --------------------------------
__global__ void k_detect(const int* __restrict__ ei) {
    if (threadIdx.x == 0 && blockIdx.x == 0) {
        int is64 = 1;
        #pragma unroll
        for (int i = 0; i < 16; i++)
            if (ei[2 * i + 1] != 0) is64 = 0;
        g_is64 = is64;
    }
}

__device__ __forceinline__ int load_idx(const void* ei, long long pos) {
    if (g_is64) return (int)((const long long*)ei)[pos];
    return ((const int*)ei)[pos];
}

// ---------------- pre-pass: degrees, dinv, CSR ------------------------------
__global__ void k_zero_deg(int n) {
    int i = blockIdx.x * blockDim.x + threadIdx.x;
    if (i < n) g_deg[i] = 0;
}

__global__ void k_deg(const void* __restrict__ ei, int e, int n) {
    int i = blockIdx.x * blockDim.x + threadIdx.x;
    if (i < e) {
        int dst = load_idx(ei, (long long)e + i);
        if ((unsigned)dst < (unsigned)n)
            atomicAdd(&g_deg[dst], 1);
    }
}

__global__ void k_dinv(int n) {
    int i = blockIdx.x * blockDim.x + threadIdx.x;
    if (i < n) g_dinv[i] = rsqrtf((float)(g_deg[i] + 1));   // +1 self loop
}

__global__ void k_scan_a(int n) {
    __shared__ int s[1024];
    int t = threadIdx.x;
    int i = blockIdx.x * 1024 + t;
    int v = (i < n) ? g_deg[i] : 0;
    s[t] = v;
    __syncthreads();
    for (int off = 1; off < 1024; off <<= 1) {
        int u = (t >= off) ? s[t - off] : 0;
        __syncthreads();
        s[t] += u;
        __syncthreads();
    }
    if (i < n) g_incl[i] = s[t];
    if (t == 1023) g_bsum[blockIdx.x] = s[1023];
}

__global__ void k_scan_b(int nb) {
    if (threadIdx.x == 0) {
        int acc = 0;
        for (int b = 0; b < nb; b++) { g_boff[b] = acc; acc += g_bsum[b]; }
    }
}

__global__ void k_scan_c(int n) {
    int i = blockIdx.x * blockDim.x + threadIdx.x;
    if (i < n) {
        int st = g_incl[i] + g_boff[i >> 10] - g_deg[i];
        g_start[i]  = st;
        g_cursor[i] = st;
    }
}

__global__ void k_fill(const void* __restrict__ ei, int e, int n) {
    int i = blockIdx.x * blockDim.x + threadIdx.x;
    if (i < e) {
        int s = load_idx(ei, i);
        int d = load_idx(ei, (long long)e + i);
        if ((unsigned)s < (unsigned)n && (unsigned)d < (unsigned)n) {
            int p = atomicAdd(&g_cursor[d], 1);
            if ((unsigned)p < (unsigned)EE) {
                g_csr_src[p] = s;
                g_csr_w[p]   = g_dinv[s] * g_dinv[d];
            }
        }
    }
}

// ============================================================================
// Tensor-core GEMM (mma.sync bf16, fp32 accum), 3-term split.
// Tile-blocked smem layout: 8x8 bf16 tile = 128 B; element (r,c) ->
//   ((r>>3)*16 + (c>>3))*128 + (r&7)*16 + (c&7)*2     (K=128 -> 16 k-tiles)
// Per CTA: 64(M) x 128(N); 128 threads (4 warps, each 32M x 64N); 96 KB smem
// -> 2 CTAs/SM so staging overlaps MMA across CTAs.
// ============================================================================

#define MM_A_HI 0
#define MM_A_LO 16384
#define MM_B_HI 32768
#define MM_B_LO 65536
#define MM_SMEM 98304

__device__ __forceinline__ int blk_off(int r, int c) {
    return (((r >> 3) * 16 + (c >> 3)) << 7) + ((r & 7) << 4) + ((c & 7) << 1);
}

__device__ __forceinline__ unsigned mm_s2u(const void* p) {
    unsigned a;
    asm("{ .reg .u64 t; cvta.to.shared.u64 t, %1; cvt.u32.u64 %0, t; }"
        : "=r"(a) : "l"(p));
    return a;
}

__device__ __forceinline__ void ldm_x4(unsigned r[4], unsigned addr) {
    asm volatile("ldmatrix.sync.aligned.m8n8.x4.shared.b16 {%0,%1,%2,%3}, [%4];"
                 : "=r"(r[0]), "=r"(r[1]), "=r"(r[2]), "=r"(r[3]) : "r"(addr));
}

__device__ __forceinline__ void mma16816(float c[4], const unsigned a[4],
                                         unsigned b0, unsigned b1) {
    asm volatile(
        "mma.sync.aligned.m16n8k16.row.col.f32.bf16.bf16.f32 "
        "{%0,%1,%2,%3}, {%4,%5,%6,%7}, {%8,%9}, {%0,%1,%2,%3};"
        : "+f"(c[0]), "+f"(c[1]), "+f"(c[2]), "+f"(c[3])
        : "r"(a[0]), "r"(a[1]), "r"(a[2]), "r"(a[3]), "r"(b0), "r"(b1));
}

__device__ __forceinline__ void mm_split(float v, unsigned short& h,
                                         unsigned short& l) {
    __nv_bfloat16 bh = __float2bfloat16(v);
    float rem = v - __bfloat162float(bh);
    __nv_bfloat16 bl = __float2bfloat16(rem);
    h = __bfloat16_as_ushort(bh);
    l = __bfloat16_as_ushort(bl);
}

// one-time W split: out layout row = out-channel n, col = k, tile-blocked
__global__ void k_wsplit(const float* __restrict__ W0,
                         const float* __restrict__ Wmid,
                         const float* __restrict__ Wlast) {
    int i = blockIdx.x * blockDim.x + threadIdx.x;
    if (i >= 6 * D * D) return;
    int l   = i / (D * D);
    int rem = i - l * D * D;
    int k   = rem >> 7;          // rem / 128
    int nr  = rem & 127;         // coalesced over n
    const float* W = (l == 0) ? W0 : ((l < 5) ? (Wmid + (size_t)(l - 1) * D * D)
                                              : Wlast);
    float v = W[(size_t)k * D + nr];
    unsigned short h, lo;
    mm_split(v, h, lo);
    int off = blk_off(nr, k);    // bytes within layer
    *(unsigned short*)((char*)g_wh + (size_t)l * 32768 + off) = h;
    *(unsigned short*)((char*)g_wl + (size_t)l * 32768 + off) = lo;
}

__device__ __forceinline__ const float* sel_x(int s, const float* ext) {
    return (s == 0) ? ext : ((s == 1) ? g_xa : g_xb);
}

__global__ __launch_bounds__(128)
void k_gemm_mma(int xsel, const float* __restrict__ xext, int layer, int n) {
    extern __shared__ char sm[];
    unsigned sb = mm_s2u(sm);
    int tid  = threadIdx.x;
    int wid  = tid >> 5;
    int lane = tid & 31;
    const float* x = sel_x(xsel, xext);
    int m0 = blockIdx.x * 64;

    // ---- stage B: flat coalesced copy of precomputed splits (32 KB each) ----
    {
        const uint4* srcH = (const uint4*)((const char*)g_wh + (size_t)layer * 32768);
        const uint4* srcL = (const uint4*)((const char*)g_wl + (size_t)layer * 32768);
        uint4* dstH = (uint4*)(sm + MM_B_HI);
        uint4* dstL = (uint4*)(sm + MM_B_LO);
        #pragma unroll
        for (int it = 0; it < 16; it++) {
            int idx = it * 128 + tid;
            dstH[idx] = srcH[idx];
            dstL[idx] = srcL[idx];
        }
    }

    // ---- stage A (x tile, 64 rows): thread = (row, col-half) ----
    {
        int r  = tid >> 1;
        int c0 = (tid & 1) * 64;
        int row = m0 + r;
        bool ok = (row < n);
        const float4* xr = (const float4*)(x + (size_t)(ok ? row : 0) * D + c0);
        char* ah = sm + MM_A_HI;
        char* al = sm + MM_A_LO;
        #pragma unroll
        for (int c = 0; c < 64; c += 4) {
            float4 v = make_float4(0.f, 0.f, 0.f, 0.f);
            if (ok) v = xr[c >> 2];
            unsigned short h0, h1, h2, h3, l0, l1, l2, l3;
            mm_split(v.x, h0, l0); mm_split(v.y, h1, l1);
            mm_split(v.z, h2, l2); mm_split(v.w, h3, l3);
            uint2 hp, lp;
            hp.x = (unsigned)h0 | ((unsigned)h1 << 16);
            hp.y = (unsigned)h2 | ((unsigned)h3 << 16);
            lp.x = (unsigned)l0 | ((unsigned)l1 << 16);
            lp.y = (unsigned)l2 | ((unsigned)l3 << 16);
            int off = blk_off(r, c0 + c);
            *(uint2*)(ah + off) = hp;
            *(uint2*)(al + off) = lp;
        }
    }
    __syncthreads();

    // ---- warp tile: 32 (M) x 64 (N) ----
    int wm = (wid & 1) * 32;
    int wn = (wid >> 1) * 64;

    float c[2][8][4];
    #pragma unroll
    for (int mi = 0; mi < 2; mi++)
        #pragma unroll
        for (int nb = 0; nb < 8; nb++)
            #pragma unroll
            for (int q = 0; q < 4; q++) c[mi][nb][q] = 0.f;

    // lane -> tile addressing for ldmatrix x4 (16x16 fragment)
    //  A frag (mf, kf): tile_r = mf/8 + ((lane>>3)&1), tile_c = kf/8 + (lane>>4)
    //  B frag (nf, kf): tile_r = nf/8 + (lane>>4),     tile_c = kf/8 + ((lane>>3)&1)
    int aTR = (lane >> 3) & 1;
    int aTC = lane >> 4;
    int bTR = lane >> 4;
    int bTC = (lane >> 3) & 1;
    int rw  = (lane & 7) << 4;

    #pragma unroll
    for (int term = 0; term < 3; term++) {
        unsigned aT = sb + ((term == 1) ? MM_A_LO : MM_A_HI);
        unsigned bT = sb + ((term == 2) ? MM_B_LO : MM_B_HI);
        unsigned a0Base = aT + (unsigned)((((wm >> 3) + aTR) * 16 + aTC) << 7) + rw;
        unsigned a1Base = a0Base + (2u * 16u << 7);          // +16 rows = +2 tile rows
        unsigned bBase  = bT + (unsigned)((((wn >> 3) + bTR) * 16 + bTC) << 7) + rw;

        #pragma unroll
        for (int k = 0; k < 8; k++) {
            unsigned kOff = (unsigned)(k * 2) << 7;          // +2 k-tiles per k-step
            unsigned a0[4], a1[4];
            ldm_x4(a0, a0Base + kOff);
            ldm_x4(a1, a1Base + kOff);
            #pragma unroll
            for (int nb = 0; nb < 4; nb++) {
                unsigned b[4];
                ldm_x4(b, bBase + (unsigned)(nb * 2 * 16 << 7) + kOff);
                mma16816(c[0][2 * nb],     a0, b[0], b[1]);
                mma16816(c[0][2 * nb + 1], a0, b[2], b[3]);
                mma16816(c[1][2 * nb],     a1, b[0], b[1]);
                mma16816(c[1][2 * nb + 1], a1, b[2], b[3]);
            }
        }
    }

    // ---- epilogue: write fragments to g_h ----
    #pragma unroll
    for (int mi = 0; mi < 2; mi++) {
        int rowA = m0 + wm + mi * 16 + (lane >> 2);
        int rowB = rowA + 8;
        #pragma unroll
        for (int nb = 0; nb < 8; nb++) {
            int col = wn + nb * 8 + (lane & 3) * 2;
            if (rowA < n) {
                float2 v = make_float2(c[mi][nb][0], c[mi][nb][1]);
                *(float2*)(g_h + (size_t)rowA * D + col) = v;
            }
            if (rowB < n) {
                float2 v = make_float2(c[mi][nb][2], c[mi][nb][3]);
                *(float2*)(g_h + (size_t)rowB * D + col) = v;
            }
        }
    }
}

// ---------------- aggregation: y[i] = b + dinv[i]^2*h[i] + sum w*h[src] -----
__global__ void k_gather(const float* __restrict__ bias, int ysel,
                         float* __restrict__ yext, int n) {
    int gw   = (blockIdx.x * blockDim.x + threadIdx.x) >> 5;
    int lane = threadIdx.x & 31;
    if (gw >= n) return;
    int i = gw;
    float* y = (ysel == 0) ? g_y : yext;

    float dv = g_dinv[i];
    float4 acc = ((const float4*)bias)[lane];
    float4 hv  = ((const float4*)(g_h + (size_t)i * D))[lane];
    float c = dv * dv;
    acc.x += c * hv.x; acc.y += c * hv.y; acc.z += c * hv.z; acc.w += c * hv.w;

    int j = g_start[i];
    int e = j + g_deg[i];
    if (e > EE) e = EE;
    if (j < e) {
        int   src = g_csr_src[j];
        float w   = g_csr_w[j];
        while (j < e) {
            int nj = j + 1;
            int nsrc = 0; float nw = 0.f;
            if (nj < e) { nsrc = g_csr_src[nj]; nw = g_csr_w[nj]; }
            float4 hs = ((const float4*)(g_h + (size_t)src * D))[lane];
            acc.x += w * hs.x; acc.y += w * hs.y;
            acc.z += w * hs.z; acc.w += w * hs.w;
            src = nsrc; w = nw; j = nj;
        }
    }
    ((float4*)(y + (size_t)i * D))[lane] = acc;
}

// ---------------- BatchNorm ---------------------------------------------------
__global__ void k_bnzero() {
    int c = threadIdx.x;
    g_sum[c] = 0.f; g_sq[c] = 0.f;
}

__global__ void k_stats(int n) {
    int c = threadIdx.x;
    float s = 0.f, q = 0.f;
    for (int r = blockIdx.x; r < n; r += gridDim.x) {
        float v = g_y[(size_t)r * D + c];
        s += v; q += v * v;
    }
    atomicAdd(&g_sum[c], s);
    atomicAdd(&g_sq[c],  q);
}

__global__ void k_bnfin(const float* __restrict__ gamma,
                        const float* __restrict__ beta, float inv_n) {
    int c = threadIdx.x;
    float mu  = g_sum[c] * inv_n;
    float var = g_sq[c] * inv_n - mu * mu;
    float sc  = gamma[c] * rsqrtf(var + BN_EPS);
    g_scale[c] = sc;
    g_shift[c] = beta[c] - mu * sc;
}

__global__ void k_norm(int resSel, int outSel, int total4) {
    int i = blockIdx.x * blockDim.x + threadIdx.x;
    if (i >= total4) return;
    int c4 = i & (D / 4 - 1);
    float4 v  = ((const float4*)g_y)[i];
    float4 sc = ((const float4*)g_scale)[c4];
    float4 sh = ((const float4*)g_shift)[c4];
    v.x = fmaxf(v.x * sc.x + sh.x, 0.f);
    v.y = fmaxf(v.y * sc.y + sh.y, 0.f);
    v.z = fmaxf(v.z * sc.z + sh.z, 0.f);
    v.w = fmaxf(v.w * sc.w + sh.w, 0.f);
    if (resSel) {
        const float4* res = (resSel == 1) ? (const float4*)g_xa : (const float4*)g_xb;
        float4 rv = res[i];
        v.x += rv.x; v.y += rv.y; v.z += rv.z; v.w += rv.w;
    }
    float4* out = (outSel == 1) ? (float4*)g_xa : (float4*)g_xb;
    out[i] = v;
}

// ---------------- launch ------------------------------------------------------
extern "C" void kernel_launch(void* const* d_in, const int* in_sizes, int n_in,
                              void* d_out, int out_size) {
    const float* x     = (const float*)d_in[0];
    const void*  ei    = d_in[1];
    const float* W0    = (const float*)d_in[2];
    const float* b0    = (const float*)d_in[3];
    const float* Wmid  = (const float*)d_in[4];
    const float* bmid  = (const float*)d_in[5];
    const float* Wlast = (const float*)d_in[6];
    const float* blast = (const float*)d_in[7];
    const float* gamma = (const float*)d_in[8];
    const float* beta  = (const float*)d_in[9];

    int n = in_sizes[0] / D;
    int e = in_sizes[1] / 2;

    cudaFuncSetAttribute(k_gemm_mma, cudaFuncAttributeMaxDynamicSharedMemorySize,
                         MM_SMEM);

    int nTiles     = (n + 63) / 64;
    int gatherGrid = (n * 32 + 255) / 256;
    int total4     = n * (D / 4);
    int normGrid   = (total4 + 255) / 256;

    // ---- launches ordered so that layer-0 GEMM is the 4th launch (ncu -s) ----
    k_detect<<<1, 32>>>((const int*)ei);                               // 1
    k_wsplit<<<(6 * D * D + 255) / 256, 256>>>(W0, Wmid, Wlast);       // 2
    k_zero_deg<<<(n + 255) / 256, 256>>>(n);                           // 3
    k_gemm_mma<<<nTiles, 128, MM_SMEM>>>(0, x, 0, n);                  // 4 <- profiled
    k_deg<<<(e + 255) / 256, 256>>>(ei, e, n);                         // 5
    k_dinv<<<(n + 255) / 256, 256>>>(n);                               // 6
    int nb = (n + 1023) / 1024;
    k_scan_a<<<nb, 1024>>>(n);
    k_scan_b<<<1, 32>>>(nb);
    k_scan_c<<<(n + 255) / 256, 256>>>(n);
    k_fill<<<(e + 255) / 256, 256>>>(ei, e, n);

    // ---- layer 0 (no residual) ----
    k_gather<<<gatherGrid, 256>>>(b0, 0, nullptr, n);
    k_bnzero<<<1, D>>>();
    k_stats<<<1024, D>>>(n);
    k_bnfin<<<1, D>>>(gamma, beta, 1.0f / n);
    k_norm<<<normGrid, 256>>>(0, 1, total4);    // -> g_xa

    // ---- middle layers (residual) ----
    int xs = 1;
    for (int i = 0; i < 4; i++) {
        k_gemm_mma<<<nTiles, 128, MM_SMEM>>>(xs, x, i + 1, n);
        k_gather<<<gatherGrid, 256>>>(bmid + (size_t)i * D, 0, nullptr, n);
        k_bnzero<<<1, D>>>();
        k_stats<<<1024, D>>>(n);
        k_bnfin<<<1, D>>>(gamma + (size_t)(i + 1) * D, beta + (size_t)(i + 1) * D,
                          1.0f / n);
        k_norm<<<normGrid, 256>>>(xs, 3 - xs, total4);
        xs = 3 - xs;
    }

    // ---- output layer: GEMM + aggregation straight into d_out ----
    k_gemm_mma<<<nTiles, 128, MM_SMEM>>>(xs, x, 5, n);
    k_gather<<<gatherGrid, 256>>>(blast, 1, (float*)d_out, n);
}

// round 15
// speedup vs baseline: 1.2854x; 1.2854x over previous
#include <cuda_runtime.h>
#include <cuda_bf16.h>
#include <math.h>

#define NN 100000
#define EE 1600000
#define D  128
#define BN_EPS 1e-5f

// ---------------- scratch (device globals; allocation-free kernel_launch) ----
__device__ float g_h [NN * D];
__device__ float g_y [NN * D];
__device__ float g_xa[NN * D];
__device__ float g_xb[NN * D];

__device__ int   g_deg[NN];
__device__ float g_dinv[NN];
__device__ int   g_incl[NN];
__device__ int   g_start[NN];
__device__ int   g_cursor[NN];
__device__ int   g_bsum[256];
__device__ int   g_boff[256];

__device__ int   g_csr_src[EE];
__device__ float g_csr_w [EE];

__device__ float g_sum[D], g_sq[D], g_scale[D], g_shift[D];

__device__ int   g_is64;

// ---------------- edge-index dtype detection --------------------------------
__global__ void k_detect(const int* __restrict__ ei) {
    if (threadIdx.x == 0 && blockIdx.x == 0) {
        int is64 = 1;
        #pragma unroll
        for (int i = 0; i < 16; i++)
            if (ei[2 * i + 1] != 0) is64 = 0;
        g_is64 = is64;
    }
}

__device__ __forceinline__ int load_idx(const void* ei, long long pos) {
    if (g_is64) return (int)((const long long*)ei)[pos];
    return ((const int*)ei)[pos];
}

// ---------------- pre-pass: degrees, dinv, CSR ------------------------------
__global__ void k_zero_deg(int n) {
    int i = blockIdx.x * blockDim.x + threadIdx.x;
    if (i < n) g_deg[i] = 0;
}

__global__ void k_deg(const void* __restrict__ ei, int e, int n) {
    int i = blockIdx.x * blockDim.x + threadIdx.x;
    if (i < e) {
        int dst = load_idx(ei, (long long)e + i);
        if ((unsigned)dst < (unsigned)n)
            atomicAdd(&g_deg[dst], 1);
    }
}

__global__ void k_dinv(int n) {
    int i = blockIdx.x * blockDim.x + threadIdx.x;
    if (i < n) g_dinv[i] = rsqrtf((float)(g_deg[i] + 1));   // +1 self loop
}

__global__ void k_scan_a(int n) {
    __shared__ int s[1024];
    int t = threadIdx.x;
    int i = blockIdx.x * 1024 + t;
    int v = (i < n) ? g_deg[i] : 0;
    s[t] = v;
    __syncthreads();
    for (int off = 1; off < 1024; off <<= 1) {
        int u = (t >= off) ? s[t - off] : 0;
        __syncthreads();
        s[t] += u;
        __syncthreads();
    }
    if (i < n) g_incl[i] = s[t];
    if (t == 1023) g_bsum[blockIdx.x] = s[1023];
}

__global__ void k_scan_b(int nb) {
    if (threadIdx.x == 0) {
        int acc = 0;
        for (int b = 0; b < nb; b++) { g_boff[b] = acc; acc += g_bsum[b]; }
    }
}

__global__ void k_scan_c(int n) {
    int i = blockIdx.x * blockDim.x + threadIdx.x;
    if (i < n) {
        int st = g_incl[i] + g_boff[i >> 10] - g_deg[i];
        g_start[i]  = st;
        g_cursor[i] = st;
    }
}

__global__ void k_fill(const void* __restrict__ ei, int e, int n) {
    int i = blockIdx.x * blockDim.x + threadIdx.x;
    if (i < e) {
        int s = load_idx(ei, i);
        int d = load_idx(ei, (long long)e + i);
        if ((unsigned)s < (unsigned)n && (unsigned)d < (unsigned)n) {
            int p = atomicAdd(&g_cursor[d], 1);
            if ((unsigned)p < (unsigned)EE) {
                g_csr_src[p] = s;
                g_csr_w[p]   = g_dinv[s] * g_dinv[d];
            }
        }
    }
}

// ============================================================================
// Tensor-core GEMM via mma.sync (bf16, fp32 accum) — R8 version (known good).
// h = x @ W, fp32 emulated with 3-term bf16 split: xh*wh + xl*wh + xh*wl.
// Per CTA: 128x128 M-tile; 8 warps, each 32(M) x 64(N).
// ============================================================================

#define MM_STRIDE 136                       // bf16 elems/row (+8 pad), 272 B
#define MM_ROWB   (MM_STRIDE * 2)
#define MM_TILE   (128 * MM_ROWB)           // 34816 B
#define MM_A_HI   0
#define MM_A_LO   MM_TILE
#define MM_B_HI   (2 * MM_TILE)
#define MM_B_LO   (3 * MM_TILE)
#define MM_SMEM   (4 * MM_TILE)             // 139264 B

__device__ __forceinline__ unsigned mm_s2u(const void* p) {
    unsigned a;
    asm("{ .reg .u64 t; cvta.to.shared.u64 t, %1; cvt.u32.u64 %0, t; }"
        : "=r"(a) : "l"(p));
    return a;
}

__device__ __forceinline__ void ldm_x4(unsigned r[4], unsigned addr) {
    asm volatile("ldmatrix.sync.aligned.m8n8.x4.shared.b16 {%0,%1,%2,%3}, [%4];"
                 : "=r"(r[0]), "=r"(r[1]), "=r"(r[2]), "=r"(r[3]) : "r"(addr));
}

__device__ __forceinline__ void mma16816(float c[4], const unsigned a[4],
                                         unsigned b0, unsigned b1) {
    asm volatile(
        "mma.sync.aligned.m16n8k16.row.col.f32.bf16.bf16.f32 "
        "{%0,%1,%2,%3}, {%4,%5,%6,%7}, {%8,%9}, {%0,%1,%2,%3};"
        : "+f"(c[0]), "+f"(c[1]), "+f"(c[2]), "+f"(c[3])
        : "r"(a[0]), "r"(a[1]), "r"(a[2]), "r"(a[3]), "r"(b0), "r"(b1));
}

__device__ __forceinline__ void mm_split(float v, unsigned short& h,
                                         unsigned short& l) {
    __nv_bfloat16 bh = __float2bfloat16(v);
    float rem = v - __bfloat162float(bh);
    __nv_bfloat16 bl = __float2bfloat16(rem);
    h = __bfloat16_as_ushort(bh);
    l = __bfloat16_as_ushort(bl);
}

__device__ __forceinline__ const float* sel_x(int s, const float* ext) {
    return (s == 0) ? ext : ((s == 1) ? g_xa : g_xb);
}

__global__ __launch_bounds__(256)
void k_gemm_mma(int xsel, const float* __restrict__ xext,
                const float* __restrict__ W, int n) {
    extern __shared__ char sm[];
    unsigned sb = mm_s2u(sm);
    int tid  = threadIdx.x;
    int wid  = tid >> 5;
    int lane = tid & 31;
    const float* x = sel_x(xsel, xext);
    int m0 = blockIdx.x * 128;

    // ---- stage A (x tile): thread = (row, col-half); split fp32 -> hi/lo ----
    {
        int r  = tid >> 1;
        int c0 = (tid & 1) * 64;
        int row = m0 + r;
        bool ok = (row < n);
        const float4* xr = (const float4*)(x + (size_t)(ok ? row : 0) * D + c0);
        char* ah = sm + MM_A_HI + r * MM_ROWB + c0 * 2;
        char* al = sm + MM_A_LO + r * MM_ROWB + c0 * 2;
        #pragma unroll
        for (int c = 0; c < 64; c += 4) {
            float4 v = make_float4(0.f, 0.f, 0.f, 0.f);
            if (ok) v = xr[c >> 2];
            unsigned short h0, h1, h2, h3, l0, l1, l2, l3;
            mm_split(v.x, h0, l0); mm_split(v.y, h1, l1);
            mm_split(v.z, h2, l2); mm_split(v.w, h3, l3);
            uint2 hp, lp;
            hp.x = (unsigned)h0 | ((unsigned)h1 << 16);
            hp.y = (unsigned)h2 | ((unsigned)h3 << 16);
            lp.x = (unsigned)l0 | ((unsigned)l1 << 16);
            lp.y = (unsigned)l2 | ((unsigned)l3 << 16);
            *(uint2*)(ah + c * 2) = hp;
            *(uint2*)(al + c * 2) = lp;
        }
    }

    // ---- stage B = W^T (row = out-channel, col = k) ----
    {
        int nn_ = tid >> 1;
        int k0  = (tid & 1) * 64;
        char* bh = sm + MM_B_HI + nn_ * MM_ROWB + k0 * 2;
        char* bl = sm + MM_B_LO + nn_ * MM_ROWB + k0 * 2;
        #pragma unroll 8
        for (int k = 0; k < 64; k += 2) {
            float w0 = W[(size_t)(k0 + k)     * D + nn_];
            float w1 = W[(size_t)(k0 + k + 1) * D + nn_];
            unsigned short h0, h1, l0, l1;
            mm_split(w0, h0, l0); mm_split(w1, h1, l1);
            *(unsigned*)(bh + k * 2) = (unsigned)h0 | ((unsigned)h1 << 16);
            *(unsigned*)(bl + k * 2) = (unsigned)l0 | ((unsigned)l1 << 16);
        }
    }
    __syncthreads();

    // ---- warp tile: 32 (M) x 64 (N) ----
    int wm = (wid & 3) * 32;
    int wn = (wid >> 2) * 64;

    float c[2][8][4];
    #pragma unroll
    for (int mi = 0; mi < 2; mi++)
        #pragma unroll
        for (int nb = 0; nb < 8; nb++)
            #pragma unroll
            for (int q = 0; q < 4; q++) c[mi][nb][q] = 0.f;

    int aRow = lane & 15;
    int aKof = (lane >> 4) << 3;
    int bRow = (lane & 7) + ((lane >> 4) << 3);
    int bKof = (lane & 8);

    unsigned aBase0 = sb + MM_A_HI;
    #pragma unroll
    for (int term = 0; term < 3; term++) {
        unsigned aT = aBase0 + ((term == 1) ? (MM_A_LO - MM_A_HI) : 0);
        unsigned bT = sb + ((term == 2) ? MM_B_LO : MM_B_HI);
        unsigned aAdr0 = aT + (wm + aRow) * MM_ROWB + aKof * 2;
        unsigned aAdr1 = aAdr0 + 16 * MM_ROWB;
        unsigned bAdr  = bT + (wn + bRow) * MM_ROWB + bKof * 2;

        #pragma unroll
        for (int k = 0; k < 8; k++) {
            unsigned a0[4], a1[4];
            ldm_x4(a0, aAdr0 + k * 32);
            ldm_x4(a1, aAdr1 + k * 32);
            #pragma unroll
            for (int nb = 0; nb < 4; nb++) {
                unsigned b[4];
                ldm_x4(b, bAdr + nb * 16 * MM_ROWB + k * 32);
                mma16816(c[0][2 * nb],     a0, b[0], b[1]);
                mma16816(c[0][2 * nb + 1], a0, b[2], b[3]);
                mma16816(c[1][2 * nb],     a1, b[0], b[1]);
                mma16816(c[1][2 * nb + 1], a1, b[2], b[3]);
            }
        }
    }

    // ---- epilogue: write fragments to g_h ----
    #pragma unroll
    for (int mi = 0; mi < 2; mi++) {
        int rowA = m0 + wm + mi * 16 + (lane >> 2);
        int rowB = rowA + 8;
        #pragma unroll
        for (int nb = 0; nb < 8; nb++) {
            int col = wn + nb * 8 + (lane & 3) * 2;
            if (rowA < n) {
                float2 v = make_float2(c[mi][nb][0], c[mi][nb][1]);
                *(float2*)(g_h + (size_t)rowA * D + col) = v;
            }
            if (rowB < n) {
                float2 v = make_float2(c[mi][nb][2], c[mi][nb][3]);
                *(float2*)(g_h + (size_t)rowB * D + col) = v;
            }
        }
    }
}

// ============================================================================
// aggregation (warp per node, 4-way edge unroll for MLP) + fused BN stats
// y[i] = b + dinv[i]^2*h[i] + sum_j w_j*h[src_j]
// ============================================================================
__global__ __launch_bounds__(256)
void k_gather(const float* __restrict__ bias, int ysel,
              float* __restrict__ yext, int n, int doStats) {
    __shared__ float sS[8][128];
    __shared__ float sQ[8][128];
    int tid  = threadIdx.x;
    int wid  = tid >> 5;
    int lane = tid & 31;
    int gw   = (blockIdx.x * blockDim.x + tid) >> 5;
    bool active = (gw < n);

    float4 acc = make_float4(0.f, 0.f, 0.f, 0.f);
    if (active) {
        int i = gw;
        float dv = g_dinv[i];
        float4 b4 = ((const float4*)bias)[lane];
        float4 hv = ((const float4*)(g_h + (size_t)i * D))[lane];
        float cc = dv * dv;
        acc.x = b4.x + cc * hv.x;
        acc.y = b4.y + cc * hv.y;
        acc.z = b4.z + cc * hv.z;
        acc.w = b4.w + cc * hv.w;

        float4 a1 = make_float4(0.f, 0.f, 0.f, 0.f);
        float4 a2 = make_float4(0.f, 0.f, 0.f, 0.f);
        float4 a3 = make_float4(0.f, 0.f, 0.f, 0.f);

        int j = g_start[i];
        int e = j + g_deg[i];
        if (e > EE) e = EE;

        for (; j + 3 < e; j += 4) {
            int   s0 = g_csr_src[j],   s1 = g_csr_src[j+1];
            int   s2 = g_csr_src[j+2], s3 = g_csr_src[j+3];
            float w0 = g_csr_w[j],     w1 = g_csr_w[j+1];
            float w2 = g_csr_w[j+2],   w3 = g_csr_w[j+3];
            float4 h0 = ((const float4*)(g_h + (size_t)s0 * D))[lane];
            float4 h1 = ((const float4*)(g_h + (size_t)s1 * D))[lane];
            float4 h2 = ((const float4*)(g_h + (size_t)s2 * D))[lane];
            float4 h3 = ((const float4*)(g_h + (size_t)s3 * D))[lane];
            acc.x += w0 * h0.x; acc.y += w0 * h0.y;
            acc.z += w0 * h0.z; acc.w += w0 * h0.w;
            a1.x  += w1 * h1.x; a1.y  += w1 * h1.y;
            a1.z  += w1 * h1.z; a1.w  += w1 * h1.w;
            a2.x  += w2 * h2.x; a2.y  += w2 * h2.y;
            a2.z  += w2 * h2.z; a2.w  += w2 * h2.w;
            a3.x  += w3 * h3.x; a3.y  += w3 * h3.y;
            a3.z  += w3 * h3.z; a3.w  += w3 * h3.w;
        }
        for (; j < e; j++) {
            int   s = g_csr_src[j];
            float w = g_csr_w[j];
            float4 hs = ((const float4*)(g_h + (size_t)s * D))[lane];
            acc.x += w * hs.x; acc.y += w * hs.y;
            acc.z += w * hs.z; acc.w += w * hs.w;
        }
        acc.x += a1.x + a2.x + a3.x;
        acc.y += a1.y + a2.y + a3.y;
        acc.z += a1.z + a2.z + a3.z;
        acc.w += a1.w + a2.w + a3.w;

        float* y = (ysel == 0) ? g_y : yext;
        ((float4*)(y + (size_t)i * D))[lane] = acc;
    }

    if (doStats) {                     // uniform branch: barriers are safe
        int c0 = lane * 4;
        sS[wid][c0 + 0] = acc.x;  sS[wid][c0 + 1] = acc.y;
        sS[wid][c0 + 2] = acc.z;  sS[wid][c0 + 3] = acc.w;
        sQ[wid][c0 + 0] = acc.x * acc.x;  sQ[wid][c0 + 1] = acc.y * acc.y;
        sQ[wid][c0 + 2] = acc.z * acc.z;  sQ[wid][c0 + 3] = acc.w * acc.w;
        __syncthreads();
        if (tid < 128) {
            float s = 0.f, q = 0.f;
            #pragma unroll
            for (int w = 0; w < 8; w++) { s += sS[w][tid]; q += sQ[w][tid]; }
            atomicAdd(&g_sum[tid], s);
            atomicAdd(&g_sq[tid],  q);
        }
    }
}

// ---------------- BatchNorm ---------------------------------------------------
__global__ void k_bnzero() {
    int c = threadIdx.x;
    g_sum[c] = 0.f; g_sq[c] = 0.f;
}

__global__ void k_bnfin(const float* __restrict__ gamma,
                        const float* __restrict__ beta, float inv_n) {
    int c = threadIdx.x;
    float mu  = g_sum[c] * inv_n;
    float var = g_sq[c] * inv_n - mu * mu;
    float sc  = gamma[c] * rsqrtf(var + BN_EPS);
    g_scale[c] = sc;
    g_shift[c] = beta[c] - mu * sc;
}

__global__ void k_norm(int resSel, int outSel, int total4) {
    int i = blockIdx.x * blockDim.x + threadIdx.x;
    if (i >= total4) return;
    int c4 = i & (D / 4 - 1);
    float4 v  = ((const float4*)g_y)[i];
    float4 sc = ((const float4*)g_scale)[c4];
    float4 sh = ((const float4*)g_shift)[c4];
    v.x = fmaxf(v.x * sc.x + sh.x, 0.f);
    v.y = fmaxf(v.y * sc.y + sh.y, 0.f);
    v.z = fmaxf(v.z * sc.z + sh.z, 0.f);
    v.w = fmaxf(v.w * sc.w + sh.w, 0.f);
    if (resSel) {
        const float4* res = (resSel == 1) ? (const float4*)g_xa : (const float4*)g_xb;
        float4 rv = res[i];
        v.x += rv.x; v.y += rv.y; v.z += rv.z; v.w += rv.w;
    }
    float4* out = (outSel == 1) ? (float4*)g_xa : (float4*)g_xb;
    out[i] = v;
}

// ---------------- launch ------------------------------------------------------
extern "C" void kernel_launch(void* const* d_in, const int* in_sizes, int n_in,
                              void* d_out, int out_size) {
    const float* x     = (const float*)d_in[0];
    const void*  ei    = d_in[1];
    const float* W0    = (const float*)d_in[2];
    const float* b0    = (const float*)d_in[3];
    const float* Wmid  = (const float*)d_in[4];
    const float* bmid  = (const float*)d_in[5];
    const float* Wlast = (const float*)d_in[6];
    const float* blast = (const float*)d_in[7];
    const float* gamma = (const float*)d_in[8];
    const float* beta  = (const float*)d_in[9];

    int n = in_sizes[0] / D;
    int e = in_sizes[1] / 2;

    cudaFuncSetAttribute(k_gemm_mma, cudaFuncAttributeMaxDynamicSharedMemorySize,
                         MM_SMEM);

    int nTiles     = (n + 127) / 128;
    int gatherGrid = (n * 32 + 255) / 256;
    int total4     = n * (D / 4);
    int normGrid   = (total4 + 255) / 256;

    // ---- pre: dtype detect, degrees / dinv / CSR-by-dst ----
    k_detect<<<1, 32>>>((const int*)ei);
    k_zero_deg<<<(n + 255) / 256, 256>>>(n);
    k_deg<<<(e + 255) / 256, 256>>>(ei, e, n);
    k_dinv<<<(n + 255) / 256, 256>>>(n);
    int nb = (n + 1023) / 1024;
    k_scan_a<<<nb, 1024>>>(n);
    k_scan_b<<<1, 32>>>(nb);
    k_scan_c<<<(n + 255) / 256, 256>>>(n);
    k_fill<<<(e + 255) / 256, 256>>>(ei, e, n);

    // ---- layer 0 (no residual) ----
    k_gemm_mma<<<nTiles, 256, MM_SMEM>>>(0, x, W0, n);
    k_bnzero<<<1, D>>>();
    k_gather<<<gatherGrid, 256>>>(b0, 0, nullptr, n, 1);
    k_bnfin<<<1, D>>>(gamma, beta, 1.0f / n);
    k_norm<<<normGrid, 256>>>(0, 1, total4);    // -> g_xa

    // ---- middle layers (residual) ----
    int xs = 1;
    for (int i = 0; i < 4; i++) {
        k_gemm_mma<<<nTiles, 256, MM_SMEM>>>(xs, x, Wmid + (size_t)i * D * D, n);
        k_bnzero<<<1, D>>>();
        k_gather<<<gatherGrid, 256>>>(bmid + (size_t)i * D, 0, nullptr, n, 1);
        k_bnfin<<<1, D>>>(gamma + (size_t)(i + 1) * D, beta + (size_t)(i + 1) * D,
                          1.0f / n);
        k_norm<<<normGrid, 256>>>(xs, 3 - xs, total4);
        xs = 3 - xs;
    }

    // ---- output layer: GEMM + aggregation straight into d_out ----
    k_gemm_mma<<<nTiles, 256, MM_SMEM>>>(xs, x, Wlast, n);
    k_gather<<<gatherGrid, 256>>>(blast, 1, (float*)d_out, n, 0);
}

// round 16
// speedup vs baseline: 1.3366x; 1.0398x over previous
#include <cuda_runtime.h>
#include <cuda_bf16.h>
#include <cuda_fp16.h>
#include <math.h>

#define NN 100000
#define EE 1600000
#define D  128
#define BN_EPS 1e-5f

// ---------------- scratch (device globals; allocation-free kernel_launch) ----
__device__ __half g_h2[NN * D];          // fp16 GEMM output (gathered tensor)
__device__ float  g_y [NN * D];
__device__ float  g_xa[NN * D];
__device__ float  g_xb[NN * D];

__device__ int   g_deg[NN];
__device__ float g_dinv[NN];
__device__ int   g_incl[NN];
__device__ int   g_start[NN];
__device__ int   g_cursor[NN];
__device__ int   g_bsum[256];
__device__ int   g_boff[256];

__device__ int2  g_csr[EE];              // packed (src, w bits)

__device__ float g_sum[D], g_sq[D], g_scale[D], g_shift[D];

__device__ int   g_is64;

// ---------------- edge-index dtype detection --------------------------------
__global__ void k_detect(const int* __restrict__ ei) {
    if (threadIdx.x == 0 && blockIdx.x == 0) {
        int is64 = 1;
        #pragma unroll
        for (int i = 0; i < 16; i++)
            if (ei[2 * i + 1] != 0) is64 = 0;
        g_is64 = is64;
    }
}

__device__ __forceinline__ int load_idx(const void* ei, long long pos) {
    if (g_is64) return (int)((const long long*)ei)[pos];
    return ((const int*)ei)[pos];
}

// ---------------- pre-pass: degrees, dinv, CSR ------------------------------
__global__ void k_zero_deg(int n) {
    int i = blockIdx.x * blockDim.x + threadIdx.x;
    if (i < n) g_deg[i] = 0;
}

__global__ void k_deg(const void* __restrict__ ei, int e, int n) {
    int i = blockIdx.x * blockDim.x + threadIdx.x;
    if (i < e) {
        int dst = load_idx(ei, (long long)e + i);
        if ((unsigned)dst < (unsigned)n)
            atomicAdd(&g_deg[dst], 1);
    }
}

__global__ void k_dinv(int n) {
    int i = blockIdx.x * blockDim.x + threadIdx.x;
    if (i < n) g_dinv[i] = rsqrtf((float)(g_deg[i] + 1));   // +1 self loop
}

__global__ void k_scan_a(int n) {
    __shared__ int s[1024];
    int t = threadIdx.x;
    int i = blockIdx.x * 1024 + t;
    int v = (i < n) ? g_deg[i] : 0;
    s[t] = v;
    __syncthreads();
    for (int off = 1; off < 1024; off <<= 1) {
        int u = (t >= off) ? s[t - off] : 0;
        __syncthreads();
        s[t] += u;
        __syncthreads();
    }
    if (i < n) g_incl[i] = s[t];
    if (t == 1023) g_bsum[blockIdx.x] = s[1023];
}

__global__ void k_scan_b(int nb) {
    if (threadIdx.x == 0) {
        int acc = 0;
        for (int b = 0; b < nb; b++) { g_boff[b] = acc; acc += g_bsum[b]; }
    }
}

__global__ void k_scan_c(int n) {
    int i = blockIdx.x * blockDim.x + threadIdx.x;
    if (i < n) {
        int st = g_incl[i] + g_boff[i >> 10] - g_deg[i];
        g_start[i]  = st;
        g_cursor[i] = st;
    }
}

__global__ void k_fill(const void* __restrict__ ei, int e, int n) {
    int i = blockIdx.x * blockDim.x + threadIdx.x;
    if (i < e) {
        int s = load_idx(ei, i);
        int d = load_idx(ei, (long long)e + i);
        if ((unsigned)s < (unsigned)n && (unsigned)d < (unsigned)n) {
            int p = atomicAdd(&g_cursor[d], 1);
            if ((unsigned)p < (unsigned)EE) {
                float w = g_dinv[s] * g_dinv[d];
                g_csr[p] = make_int2(s, __float_as_int(w));
            }
        }
    }
}

// ============================================================================
// Tensor-core GEMM via mma.sync (bf16, fp32 accum) — R8 mainloop (known good).
// h = x @ W, fp32 emulated with 3-term bf16 split; epilogue writes fp16.
// Per CTA: 128x128 M-tile; 8 warps, each 32(M) x 64(N).
// ============================================================================

#define MM_STRIDE 136                       // bf16 elems/row (+8 pad), 272 B
#define MM_ROWB   (MM_STRIDE * 2)
#define MM_TILE   (128 * MM_ROWB)           // 34816 B
#define MM_A_HI   0
#define MM_A_LO   MM_TILE
#define MM_B_HI   (2 * MM_TILE)
#define MM_B_LO   (3 * MM_TILE)
#define MM_SMEM   (4 * MM_TILE)             // 139264 B

__device__ __forceinline__ unsigned mm_s2u(const void* p) {
    unsigned a;
    asm("{ .reg .u64 t; cvta.to.shared.u64 t, %1; cvt.u32.u64 %0, t; }"
        : "=r"(a) : "l"(p));
    return a;
}

__device__ __forceinline__ void ldm_x4(unsigned r[4], unsigned addr) {
    asm volatile("ldmatrix.sync.aligned.m8n8.x4.shared.b16 {%0,%1,%2,%3}, [%4];"
                 : "=r"(r[0]), "=r"(r[1]), "=r"(r[2]), "=r"(r[3]) : "r"(addr));
}

__device__ __forceinline__ void mma16816(float c[4], const unsigned a[4],
                                         unsigned b0, unsigned b1) {
    asm volatile(
        "mma.sync.aligned.m16n8k16.row.col.f32.bf16.bf16.f32 "
        "{%0,%1,%2,%3}, {%4,%5,%6,%7}, {%8,%9}, {%0,%1,%2,%3};"
        : "+f"(c[0]), "+f"(c[1]), "+f"(c[2]), "+f"(c[3])
        : "r"(a[0]), "r"(a[1]), "r"(a[2]), "r"(a[3]), "r"(b0), "r"(b1));
}

__device__ __forceinline__ void mm_split(float v, unsigned short& h,
                                         unsigned short& l) {
    __nv_bfloat16 bh = __float2bfloat16(v);
    float rem = v - __bfloat162float(bh);
    __nv_bfloat16 bl = __float2bfloat16(rem);
    h = __bfloat16_as_ushort(bh);
    l = __bfloat16_as_ushort(bl);
}

__device__ __forceinline__ const float* sel_x(int s, const float* ext) {
    return (s == 0) ? ext : ((s == 1) ? g_xa : g_xb);
}

__global__ __launch_bounds__(256)
void k_gemm_mma(int xsel, const float* __restrict__ xext,
                const float* __restrict__ W, int n) {
    extern __shared__ char sm[];
    unsigned sb = mm_s2u(sm);
    int tid  = threadIdx.x;
    int wid  = tid >> 5;
    int lane = tid & 31;
    const float* x = sel_x(xsel, xext);
    int m0 = blockIdx.x * 128;

    // ---- stage A (x tile): thread = (row, col-half); split fp32 -> hi/lo ----
    {
        int r  = tid >> 1;
        int c0 = (tid & 1) * 64;
        int row = m0 + r;
        bool ok = (row < n);
        const float4* xr = (const float4*)(x + (size_t)(ok ? row : 0) * D + c0);
        char* ah = sm + MM_A_HI + r * MM_ROWB + c0 * 2;
        char* al = sm + MM_A_LO + r * MM_ROWB + c0 * 2;
        #pragma unroll
        for (int c = 0; c < 64; c += 4) {
            float4 v = make_float4(0.f, 0.f, 0.f, 0.f);
            if (ok) v = xr[c >> 2];
            unsigned short h0, h1, h2, h3, l0, l1, l2, l3;
            mm_split(v.x, h0, l0); mm_split(v.y, h1, l1);
            mm_split(v.z, h2, l2); mm_split(v.w, h3, l3);
            uint2 hp, lp;
            hp.x = (unsigned)h0 | ((unsigned)h1 << 16);
            hp.y = (unsigned)h2 | ((unsigned)h3 << 16);
            lp.x = (unsigned)l0 | ((unsigned)l1 << 16);
            lp.y = (unsigned)l2 | ((unsigned)l3 << 16);
            *(uint2*)(ah + c * 2) = hp;
            *(uint2*)(al + c * 2) = lp;
        }
    }

    // ---- stage B = W^T (row = out-channel, col = k) ----
    {
        int nn_ = tid >> 1;
        int k0  = (tid & 1) * 64;
        char* bh = sm + MM_B_HI + nn_ * MM_ROWB + k0 * 2;
        char* bl = sm + MM_B_LO + nn_ * MM_ROWB + k0 * 2;
        #pragma unroll 8
        for (int k = 0; k < 64; k += 2) {
            float w0 = W[(size_t)(k0 + k)     * D + nn_];
            float w1 = W[(size_t)(k0 + k + 1) * D + nn_];
            unsigned short h0, h1, l0, l1;
            mm_split(w0, h0, l0); mm_split(w1, h1, l1);
            *(unsigned*)(bh + k * 2) = (unsigned)h0 | ((unsigned)h1 << 16);
            *(unsigned*)(bl + k * 2) = (unsigned)l0 | ((unsigned)l1 << 16);
        }
    }
    __syncthreads();

    // ---- warp tile: 32 (M) x 64 (N) ----
    int wm = (wid & 3) * 32;
    int wn = (wid >> 2) * 64;

    float c[2][8][4];
    #pragma unroll
    for (int mi = 0; mi < 2; mi++)
        #pragma unroll
        for (int nb = 0; nb < 8; nb++)
            #pragma unroll
            for (int q = 0; q < 4; q++) c[mi][nb][q] = 0.f;

    int aRow = lane & 15;
    int aKof = (lane >> 4) << 3;
    int bRow = (lane & 7) + ((lane >> 4) << 3);
    int bKof = (lane & 8);

    unsigned aBase0 = sb + MM_A_HI;
    #pragma unroll
    for (int term = 0; term < 3; term++) {
        unsigned aT = aBase0 + ((term == 1) ? (MM_A_LO - MM_A_HI) : 0);
        unsigned bT = sb + ((term == 2) ? MM_B_LO : MM_B_HI);
        unsigned aAdr0 = aT + (wm + aRow) * MM_ROWB + aKof * 2;
        unsigned aAdr1 = aAdr0 + 16 * MM_ROWB;
        unsigned bAdr  = bT + (wn + bRow) * MM_ROWB + bKof * 2;

        #pragma unroll
        for (int k = 0; k < 8; k++) {
            unsigned a0[4], a1[4];
            ldm_x4(a0, aAdr0 + k * 32);
            ldm_x4(a1, aAdr1 + k * 32);
            #pragma unroll
            for (int nb = 0; nb < 4; nb++) {
                unsigned b[4];
                ldm_x4(b, bAdr + nb * 16 * MM_ROWB + k * 32);
                mma16816(c[0][2 * nb],     a0, b[0], b[1]);
                mma16816(c[0][2 * nb + 1], a0, b[2], b[3]);
                mma16816(c[1][2 * nb],     a1, b[0], b[1]);
                mma16816(c[1][2 * nb + 1], a1, b[2], b[3]);
            }
        }
    }

    // ---- epilogue: convert fragments to fp16 and write g_h2 ----
    #pragma unroll
    for (int mi = 0; mi < 2; mi++) {
        int rowA = m0 + wm + mi * 16 + (lane >> 2);
        int rowB = rowA + 8;
        #pragma unroll
        for (int nb = 0; nb < 8; nb++) {
            int col = wn + nb * 8 + (lane & 3) * 2;
            if (rowA < n) {
                __half2 p = __floats2half2_rn(c[mi][nb][0], c[mi][nb][1]);
                *(__half2*)((char*)g_h2 + ((size_t)rowA * D + col) * 2) = p;
            }
            if (rowB < n) {
                __half2 p = __floats2half2_rn(c[mi][nb][2], c[mi][nb][3]);
                *(__half2*)((char*)g_h2 + ((size_t)rowB * D + col) * 2) = p;
            }
        }
    }
}

// ============================================================================
// aggregation (warp per node, fp16 rows, 4-way unroll) + fused BN stats
// y[i] = b + dinv[i]^2*h[i] + sum_j w_j*h[src_j]
// ============================================================================
__device__ __forceinline__ void acc_row(float4& a, uint2 bits, float w) {
    __half2 p0 = *(__half2*)&bits.x;
    __half2 p1 = *(__half2*)&bits.y;
    float2 f0 = __half22float2(p0);
    float2 f1 = __half22float2(p1);
    a.x += w * f0.x; a.y += w * f0.y;
    a.z += w * f1.x; a.w += w * f1.y;
}

__global__ __launch_bounds__(256)
void k_gather(const float* __restrict__ bias, int ysel,
              float* __restrict__ yext, int n, int doStats) {
    __shared__ float sS[8][128];
    __shared__ float sQ[8][128];
    int tid  = threadIdx.x;
    int wid  = tid >> 5;
    int lane = tid & 31;
    int gw   = (blockIdx.x * blockDim.x + tid) >> 5;
    bool active = (gw < n);

    float4 acc = make_float4(0.f, 0.f, 0.f, 0.f);
    if (active) {
        int i = gw;
        float dv = g_dinv[i];
        float4 b4 = ((const float4*)bias)[lane];
        uint2 hv = ((const uint2*)((const char*)g_h2 + (size_t)i * D * 2))[lane];
        acc = b4;
        acc_row(acc, hv, dv * dv);

        float4 a1 = make_float4(0.f, 0.f, 0.f, 0.f);
        float4 a2 = make_float4(0.f, 0.f, 0.f, 0.f);
        float4 a3 = make_float4(0.f, 0.f, 0.f, 0.f);

        int j = g_start[i];
        int e = j + g_deg[i];
        if (e > EE) e = EE;

        for (; j + 3 < e; j += 4) {
            int2 e0 = g_csr[j],     e1 = g_csr[j + 1];
            int2 e2 = g_csr[j + 2], e3 = g_csr[j + 3];
            uint2 h0 = ((const uint2*)((const char*)g_h2 + (size_t)e0.x * D * 2))[lane];
            uint2 h1 = ((const uint2*)((const char*)g_h2 + (size_t)e1.x * D * 2))[lane];
            uint2 h2 = ((const uint2*)((const char*)g_h2 + (size_t)e2.x * D * 2))[lane];
            uint2 h3 = ((const uint2*)((const char*)g_h2 + (size_t)e3.x * D * 2))[lane];
            acc_row(acc, h0, __int_as_float(e0.y));
            acc_row(a1,  h1, __int_as_float(e1.y));
            acc_row(a2,  h2, __int_as_float(e2.y));
            acc_row(a3,  h3, __int_as_float(e3.y));
        }
        for (; j < e; j++) {
            int2 ee = g_csr[j];
            uint2 hs = ((const uint2*)((const char*)g_h2 + (size_t)ee.x * D * 2))[lane];
            acc_row(acc, hs, __int_as_float(ee.y));
        }
        acc.x += a1.x + a2.x + a3.x;
        acc.y += a1.y + a2.y + a3.y;
        acc.z += a1.z + a2.z + a3.z;
        acc.w += a1.w + a2.w + a3.w;

        float* y = (ysel == 0) ? g_y : yext;
        ((float4*)(y + (size_t)i * D))[lane] = acc;
    }

    if (doStats) {                     // uniform branch: barriers are safe
        int c0 = lane * 4;
        sS[wid][c0 + 0] = acc.x;  sS[wid][c0 + 1] = acc.y;
        sS[wid][c0 + 2] = acc.z;  sS[wid][c0 + 3] = acc.w;
        sQ[wid][c0 + 0] = acc.x * acc.x;  sQ[wid][c0 + 1] = acc.y * acc.y;
        sQ[wid][c0 + 2] = acc.z * acc.z;  sQ[wid][c0 + 3] = acc.w * acc.w;
        __syncthreads();
        if (tid < 128) {
            float s = 0.f, q = 0.f;
            #pragma unroll
            for (int w = 0; w < 8; w++) { s += sS[w][tid]; q += sQ[w][tid]; }
            atomicAdd(&g_sum[tid], s);
            atomicAdd(&g_sq[tid],  q);
        }
    }
}

// ---------------- BatchNorm ---------------------------------------------------
__global__ void k_bnzero() {
    int c = threadIdx.x;
    g_sum[c] = 0.f; g_sq[c] = 0.f;
}

__global__ void k_bnfin(const float* __restrict__ gamma,
                        const float* __restrict__ beta, float inv_n) {
    int c = threadIdx.x;
    float mu  = g_sum[c] * inv_n;
    float var = g_sq[c] * inv_n - mu * mu;
    float sc  = gamma[c] * rsqrtf(var + BN_EPS);
    g_scale[c] = sc;
    g_shift[c] = beta[c] - mu * sc;
}

__global__ void k_norm(int resSel, int outSel, int total4) {
    int i = blockIdx.x * blockDim.x + threadIdx.x;
    if (i >= total4) return;
    int c4 = i & (D / 4 - 1);
    float4 v  = ((const float4*)g_y)[i];
    float4 sc = ((const float4*)g_scale)[c4];
    float4 sh = ((const float4*)g_shift)[c4];
    v.x = fmaxf(v.x * sc.x + sh.x, 0.f);
    v.y = fmaxf(v.y * sc.y + sh.y, 0.f);
    v.z = fmaxf(v.z * sc.z + sh.z, 0.f);
    v.w = fmaxf(v.w * sc.w + sh.w, 0.f);
    if (resSel) {
        const float4* res = (resSel == 1) ? (const float4*)g_xa : (const float4*)g_xb;
        float4 rv = res[i];
        v.x += rv.x; v.y += rv.y; v.z += rv.z; v.w += rv.w;
    }
    float4* out = (outSel == 1) ? (float4*)g_xa : (float4*)g_xb;
    out[i] = v;
}

// ---------------- launch ------------------------------------------------------
extern "C" void kernel_launch(void* const* d_in, const int* in_sizes, int n_in,
                              void* d_out, int out_size) {
    const float* x     = (const float*)d_in[0];
    const void*  ei    = d_in[1];
    const float* W0    = (const float*)d_in[2];
    const float* b0    = (const float*)d_in[3];
    const float* Wmid  = (const float*)d_in[4];
    const float* bmid  = (const float*)d_in[5];
    const float* Wlast = (const float*)d_in[6];
    const float* blast = (const float*)d_in[7];
    const float* gamma = (const float*)d_in[8];
    const float* beta  = (const float*)d_in[9];

    int n = in_sizes[0] / D;
    int e = in_sizes[1] / 2;

    cudaFuncSetAttribute(k_gemm_mma, cudaFuncAttributeMaxDynamicSharedMemorySize,
                         MM_SMEM);

    int nTiles     = (n + 127) / 128;
    int gatherGrid = (n * 32 + 255) / 256;
    int total4     = n * (D / 4);
    int normGrid   = (total4 + 255) / 256;

    // ---- pre: dtype detect, degrees / dinv / CSR-by-dst ----
    k_detect<<<1, 32>>>((const int*)ei);
    k_zero_deg<<<(n + 255) / 256, 256>>>(n);
    k_deg<<<(e + 255) / 256, 256>>>(ei, e, n);
    k_dinv<<<(n + 255) / 256, 256>>>(n);
    int nb = (n + 1023) / 1024;
    k_scan_a<<<nb, 1024>>>(n);
    k_scan_b<<<1, 32>>>(nb);
    k_scan_c<<<(n + 255) / 256, 256>>>(n);
    k_fill<<<(e + 255) / 256, 256>>>(ei, e, n);

    // ---- layer 0 (no residual) ----
    k_gemm_mma<<<nTiles, 256, MM_SMEM>>>(0, x, W0, n);
    k_bnzero<<<1, D>>>();
    k_gather<<<gatherGrid, 256>>>(b0, 0, nullptr, n, 1);
    k_bnfin<<<1, D>>>(gamma, beta, 1.0f / n);
    k_norm<<<normGrid, 256>>>(0, 1, total4);    // -> g_xa

    // ---- middle layers (residual) ----
    int xs = 1;
    for (int i = 0; i < 4; i++) {
        k_gemm_mma<<<nTiles, 256, MM_SMEM>>>(xs, x, Wmid + (size_t)i * D * D, n);
        k_bnzero<<<1, D>>>();
        k_gather<<<gatherGrid, 256>>>(bmid + (size_t)i * D, 0, nullptr, n, 1);
        k_bnfin<<<1, D>>>(gamma + (size_t)(i + 1) * D, beta + (size_t)(i + 1) * D,
                          1.0f / n);
        k_norm<<<normGrid, 256>>>(xs, 3 - xs, total4);
        xs = 3 - xs;
    }

    // ---- output layer: GEMM + aggregation straight into d_out ----
    k_gemm_mma<<<nTiles, 256, MM_SMEM>>>(xs, x, Wlast, n);
    k_gather<<<gatherGrid, 256>>>(blast, 1, (float*)d_out, n, 0);
}